// round 16
// baseline (speedup 1.0000x reference)
#include <cuda_runtime.h>
#include <cuda_fp16.h>
#include <cstdint>
#include <math.h>

#define MAXN 100000
#define MAXE 1600000
#define MAXG 128
#define MAXB 1024
#define XS 72   // half-element stride of smem tiles (144B rows: conflict-free ldmatrix)

// ---------------- scratch (static __device__ — zero-initialized at load) ----------------
__device__ int   g_deg[MAXN];          // zeroed by finalize of previous replay (and at load)
__device__ float g_dinv[MAXN];
__device__ int   g_rowptr[MAXN + 1];
__device__ int   g_cursor[MAXN];
__device__ int2  g_cew[MAXE];          // (col, bitcast weight)
__device__ int   g_bsums[MAXB];
__device__ float g_B1[(size_t)MAXN * 64];
__device__ float g_B2[(size_t)MAXN * 64];
__device__ float g_B3[(size_t)MAXN * 64];
__device__ float g_B4[(size_t)MAXN * 64];
__device__ __half g_F1[(size_t)MAXN * 64];   // fp16 gather operands
__device__ __half g_F2[(size_t)MAXN * 64];
__device__ __half g_feat16[(size_t)MAXN * 16];
__device__ __half g_x116[(size_t)MAXN * 16];
__device__ float g_gsum[MAXG * 64];
__device__ int   g_gcnt[MAXG];
__device__ unsigned g_epoch;
__device__ unsigned g_cnt;

// ---------------- half2 <-> float helpers ----------------
__device__ __forceinline__ float2 h2f(unsigned u) {
    __half2 h = *reinterpret_cast<__half2*>(&u);
    return __half22float2(h);
}
__device__ __forceinline__ unsigned f2h(float a, float b) {
    __half2 h = __floats2half2_rn(a, b);
    return *reinterpret_cast<unsigned*>(&h);
}

// ---------------- tensor-core primitives ----------------
__device__ __forceinline__ uint32_t smem_u32(const void* p) {
    return (uint32_t)__cvta_generic_to_shared(p);
}
__device__ __forceinline__ void ldsm_x4(unsigned r[4], uint32_t addr) {
    asm volatile("ldmatrix.sync.aligned.m8n8.x4.shared.b16 {%0,%1,%2,%3}, [%4];"
                 : "=r"(r[0]), "=r"(r[1]), "=r"(r[2]), "=r"(r[3]) : "r"(addr));
}
__device__ __forceinline__ void ldsm_x4t(unsigned r[4], uint32_t addr) {
    asm volatile("ldmatrix.sync.aligned.m8n8.x4.trans.shared.b16 {%0,%1,%2,%3}, [%4];"
                 : "=r"(r[0]), "=r"(r[1]), "=r"(r[2]), "=r"(r[3]) : "r"(addr));
}
__device__ __forceinline__ void mma16816(float c[4], const unsigned a[4], const unsigned b[2]) {
    asm volatile("mma.sync.aligned.m16n8k16.row.col.f32.f16.f16.f32 "
                 "{%0,%1,%2,%3}, {%4,%5,%6,%7}, {%8,%9}, {%0,%1,%2,%3};"
                 : "+f"(c[0]), "+f"(c[1]), "+f"(c[2]), "+f"(c[3])
                 : "r"(a[0]), "r"(a[1]), "r"(a[2]), "r"(a[3]), "r"(b[0]), "r"(b[1]));
}

// one k-step (k..k+15) for this warp's 16x32 output block
__device__ __forceinline__ void mma_step(float (*cf)[4], const __half (*XH)[XS],
                                         const __half (*WS)[XS], int m0, int n0, int k) {
    const int l = threadIdx.x & 31;
    unsigned a[4], b0[4], b1[4];
    int arow = m0 + (l & 7) + ((l >> 3) & 1) * 8;
    int acol = k + (l >> 4) * 8;
    ldsm_x4(a, smem_u32(&XH[arow][acol]));
    int brow = k + (l & 7) + ((l >> 3) & 1) * 8;
    int bc = (l >> 4) * 8;
    ldsm_x4t(b0, smem_u32(&WS[brow][n0 + bc]));
    ldsm_x4t(b1, smem_u32(&WS[brow][n0 + 16 + bc]));
    mma16816(cf[0], a, &b0[0]);
    mma16816(cf[1], a, &b0[2]);
    mma16816(cf[2], a, &b1[0]);
    mma16816(cf[3], a, &b1[2]);
}

template <int D>
__device__ __forceinline__ void mma_sweep(float (*cf)[4], const __half (*XH)[XS],
                                          const __half (*WS)[XS], int m0, int n0) {
#pragma unroll
    for (int k = 0; k < D; k += 16) mma_step(cf, XH, WS, m0, n0, k);
}

// fp32 global -> fp16 smem tile (64 x D), zero-padded rows beyond n
template <int D>
__device__ __forceinline__ void load_xtile16(const float* __restrict__ Xj, int node0, int n,
                                             __half (*XH)[XS]) {
    const int tid = threadIdx.x;
    for (int i = tid; i < 64 * (D / 2); i += 256) {
        int m = i / (D / 2), q = i % (D / 2);
        int nn = node0 + m;
        float2 v = make_float2(0.f, 0.f);
        if (nn < n) v = *(const float2*)&Xj[(size_t)nn * D + 2 * q];
        *(half2*)&XH[m][2 * q] = __floats2half2_rn(v.x, v.y);
    }
}

template <int D>
__device__ __forceinline__ void load_wtile16(const float* __restrict__ W, __half (*WS)[XS]) {
    const int tid = threadIdx.x;
    for (int i = tid; i < D * 32; i += 256) {
        int k = i >> 5, q = i & 31;
        float2 v = *(const float2*)&W[k * 64 + 2 * q];
        *(half2*)&WS[k][2 * q] = __floats2half2_rn(v.x, v.y);
    }
}

__device__ __forceinline__ void load_wtile16_sum(const float* __restrict__ A,
                                                 const float* __restrict__ B, __half (*WS)[XS]) {
    const int tid = threadIdx.x;
    for (int i = tid; i < 64 * 32; i += 256) {
        int k = i >> 5, q = i & 31;
        float2 a = *(const float2*)&A[k * 64 + 2 * q];
        float2 b = *(const float2*)&B[k * 64 + 2 * q];
        *(half2*)&WS[k][2 * q] = __floats2half2_rn(a.x + b.x, a.y + b.y);
    }
}

// ---------------- grid-wide barrier ----------------
__device__ __forceinline__ void gsync(int nb) {
    __syncthreads();
    if (threadIdx.x == 0) {
        __threadfence();                       // release
        volatile unsigned* ep = &g_epoch;
        unsigned e = *ep;
        if (atomicAdd(&g_cnt, 1u) == (unsigned)(nb - 1)) {
            g_cnt = 0;
            __threadfence();
            *ep = e + 1;
        } else {
            while (*ep == e) {}
            __threadfence();                   // acquire
        }
    }
    __syncthreads();
}

// ---------------- gather phases (fp16 operands; 8 lanes/edge x uint4) ----------------
__device__ void ph_aggr64h(const __half* __restrict__ f16, const float* __restrict__ extra,
                           float* __restrict__ out, __half* __restrict__ out16,
                           float alpha, float beta, int n, int gw, int nwarps) {
    const int lane = threadIdx.x & 31;
    const int sub = lane >> 3;        // edge slot 0..3
    const int c = (lane & 7) * 8;     // 8 halves per lane
    for (int node = gw; node < n; node += nwarps) {
        const int beg = g_rowptr[node], end = g_rowptr[node + 1];
        float acc[8];
#pragma unroll
        for (int i = 0; i < 8; i++) acc[i] = 0.f;
        for (int e = beg; e < end; e += 8) {
            int e0 = e + sub, e1 = e + 4 + sub;
            bool v0 = e0 < end, v1 = e1 < end;
            int2 ce0 = v0 ? g_cew[e0] : make_int2(0, 0);
            int2 ce1 = v1 ? g_cew[e1] : make_int2(0, 0);
            float w0 = __int_as_float(ce0.y), w1 = __int_as_float(ce1.y);
            uint4 r0 = *(const uint4*)(f16 + (size_t)ce0.x * 64 + c);
            uint4 r1 = *(const uint4*)(f16 + (size_t)ce1.x * 64 + c);
            float2 p;
            p = h2f(r0.x); acc[0] = fmaf(w0, p.x, acc[0]); acc[1] = fmaf(w0, p.y, acc[1]);
            p = h2f(r0.y); acc[2] = fmaf(w0, p.x, acc[2]); acc[3] = fmaf(w0, p.y, acc[3]);
            p = h2f(r0.z); acc[4] = fmaf(w0, p.x, acc[4]); acc[5] = fmaf(w0, p.y, acc[5]);
            p = h2f(r0.w); acc[6] = fmaf(w0, p.x, acc[6]); acc[7] = fmaf(w0, p.y, acc[7]);
            p = h2f(r1.x); acc[0] = fmaf(w1, p.x, acc[0]); acc[1] = fmaf(w1, p.y, acc[1]);
            p = h2f(r1.y); acc[2] = fmaf(w1, p.x, acc[2]); acc[3] = fmaf(w1, p.y, acc[3]);
            p = h2f(r1.z); acc[4] = fmaf(w1, p.x, acc[4]); acc[5] = fmaf(w1, p.y, acc[5]);
            p = h2f(r1.w); acc[6] = fmaf(w1, p.x, acc[6]); acc[7] = fmaf(w1, p.y, acc[7]);
        }
#pragma unroll
        for (int i = 0; i < 8; i++) {
            acc[i] += __shfl_xor_sync(0xFFFFFFFFu, acc[i], 8);
            acc[i] += __shfl_xor_sync(0xFFFFFFFFu, acc[i], 16);
        }
        if (sub == 0) {
            float s = alpha * g_dinv[node];
#pragma unroll
            for (int i = 0; i < 8; i++) acc[i] *= s;
            if (extra) {
                float4 e0v = *(const float4*)(extra + (size_t)node * 64 + c);
                float4 e1v = *(const float4*)(extra + (size_t)node * 64 + c + 4);
                acc[0] = fmaf(beta, e0v.x, acc[0]); acc[1] = fmaf(beta, e0v.y, acc[1]);
                acc[2] = fmaf(beta, e0v.z, acc[2]); acc[3] = fmaf(beta, e0v.w, acc[3]);
                acc[4] = fmaf(beta, e1v.x, acc[4]); acc[5] = fmaf(beta, e1v.y, acc[5]);
                acc[6] = fmaf(beta, e1v.z, acc[6]); acc[7] = fmaf(beta, e1v.w, acc[7]);
            }
            *(float4*)(out + (size_t)node * 64 + c) = make_float4(acc[0], acc[1], acc[2], acc[3]);
            *(float4*)(out + (size_t)node * 64 + c + 4) = make_float4(acc[4], acc[5], acc[6], acc[7]);
            if (out16)
                *(uint4*)(out16 + (size_t)node * 64 + c) =
                    make_uint4(f2h(acc[0], acc[1]), f2h(acc[2], acc[3]),
                               f2h(acc[4], acc[5]), f2h(acc[6], acc[7]));
        }
    }
}

__device__ void ph_aggr16h(const __half* __restrict__ f16, const float* __restrict__ extra,
                           float* __restrict__ out, __half* __restrict__ out16,
                           float alpha, float beta, int n, int gw, int nwarps) {
    const int lane = threadIdx.x & 31;
    const int sub = lane >> 2;
    const int c = (lane & 3) * 4;
    for (int node = gw; node < n; node += nwarps) {
        const int beg = g_rowptr[node], end = g_rowptr[node + 1];
        float4 acc = make_float4(0.f, 0.f, 0.f, 0.f);
        for (int e = beg; e < end; e += 8) {
            int ee = e + sub;
            bool v = ee < end;
            int2 ce = v ? g_cew[ee] : make_int2(0, 0);
            float w = __int_as_float(ce.y);
            uint2 r0 = *(const uint2*)(f16 + (size_t)ce.x * 16 + c);
            float2 a0 = h2f(r0.x), a1 = h2f(r0.y);
            acc.x = fmaf(w, a0.x, acc.x); acc.y = fmaf(w, a0.y, acc.y);
            acc.z = fmaf(w, a1.x, acc.z); acc.w = fmaf(w, a1.y, acc.w);
        }
#pragma unroll
        for (int o = 4; o < 32; o <<= 1) {
            acc.x += __shfl_xor_sync(0xFFFFFFFFu, acc.x, o);
            acc.y += __shfl_xor_sync(0xFFFFFFFFu, acc.y, o);
            acc.z += __shfl_xor_sync(0xFFFFFFFFu, acc.z, o);
            acc.w += __shfl_xor_sync(0xFFFFFFFFu, acc.w, o);
        }
        if (lane < 4) {
            float s = alpha * g_dinv[node];
            float4 r = make_float4(s * acc.x, s * acc.y, s * acc.z, s * acc.w);
            if (extra) {
                float4 ex = *(const float4*)(extra + (size_t)node * 16 + c);
                r.x = fmaf(beta, ex.x, r.x); r.y = fmaf(beta, ex.y, r.y);
                r.z = fmaf(beta, ex.z, r.z); r.w = fmaf(beta, ex.w, r.w);
            }
            *(float4*)(out + (size_t)node * 16 + c) = r;
            if (out16)
                *(uint2*)(out16 + (size_t)node * 16 + c) =
                    make_uint2(f2h(r.x, r.y), f2h(r.z, r.w));
        }
    }
}

// out_i = relu(U_i - min_{j->i} V16_j); 8 lanes/edge x uint4
__device__ void ph_edge_minh(const float* __restrict__ U, const __half* __restrict__ V16,
                             float* __restrict__ out, __half* __restrict__ out16,
                             int n, int gw, int nwarps) {
    const int lane = threadIdx.x & 31;
    const int sub = lane >> 3;
    const int c = (lane & 7) * 8;
    const float INF = 3.4e38f;
    for (int node = gw; node < n; node += nwarps) {
        const int beg = g_rowptr[node], end = g_rowptr[node + 1];
        float mn[8];
#pragma unroll
        for (int i = 0; i < 8; i++) mn[i] = INF;
        for (int e = beg; e < end; e += 8) {
            int e0 = e + sub, e1 = e + 4 + sub;
            bool v0 = e0 < end, v1 = e1 < end;
            int s0 = v0 ? g_cew[e0].x : 0;
            int s1 = v1 ? g_cew[e1].x : 0;
            uint4 r0 = *(const uint4*)(V16 + (size_t)s0 * 64 + c);
            uint4 r1 = *(const uint4*)(V16 + (size_t)s1 * 64 + c);
            if (v0) {
                float2 p;
                p = h2f(r0.x); mn[0] = fminf(mn[0], p.x); mn[1] = fminf(mn[1], p.y);
                p = h2f(r0.y); mn[2] = fminf(mn[2], p.x); mn[3] = fminf(mn[3], p.y);
                p = h2f(r0.z); mn[4] = fminf(mn[4], p.x); mn[5] = fminf(mn[5], p.y);
                p = h2f(r0.w); mn[6] = fminf(mn[6], p.x); mn[7] = fminf(mn[7], p.y);
            }
            if (v1) {
                float2 p;
                p = h2f(r1.x); mn[0] = fminf(mn[0], p.x); mn[1] = fminf(mn[1], p.y);
                p = h2f(r1.y); mn[2] = fminf(mn[2], p.x); mn[3] = fminf(mn[3], p.y);
                p = h2f(r1.z); mn[4] = fminf(mn[4], p.x); mn[5] = fminf(mn[5], p.y);
                p = h2f(r1.w); mn[6] = fminf(mn[6], p.x); mn[7] = fminf(mn[7], p.y);
            }
        }
#pragma unroll
        for (int i = 0; i < 8; i++) {
            mn[i] = fminf(mn[i], __shfl_xor_sync(0xFFFFFFFFu, mn[i], 8));
            mn[i] = fminf(mn[i], __shfl_xor_sync(0xFFFFFFFFu, mn[i], 16));
        }
        if (sub == 0) {
            float r[8];
            if (end > beg) {
                float4 u0 = *(const float4*)(U + (size_t)node * 64 + c);
                float4 u1 = *(const float4*)(U + (size_t)node * 64 + c + 4);
                r[0] = fmaxf(u0.x - mn[0], 0.f); r[1] = fmaxf(u0.y - mn[1], 0.f);
                r[2] = fmaxf(u0.z - mn[2], 0.f); r[3] = fmaxf(u0.w - mn[3], 0.f);
                r[4] = fmaxf(u1.x - mn[4], 0.f); r[5] = fmaxf(u1.y - mn[5], 0.f);
                r[6] = fmaxf(u1.z - mn[6], 0.f); r[7] = fmaxf(u1.w - mn[7], 0.f);
            } else {
#pragma unroll
                for (int i = 0; i < 8; i++) r[i] = 0.f;
            }
            *(float4*)(out + (size_t)node * 64 + c) = make_float4(r[0], r[1], r[2], r[3]);
            *(float4*)(out + (size_t)node * 64 + c + 4) = make_float4(r[4], r[5], r[6], r[7]);
            *(uint4*)(out16 + (size_t)node * 64 + c) =
                make_uint4(f2h(r[0], r[1]), f2h(r[2], r[3]), f2h(r[4], r[5]), f2h(r[6], r[7]));
        }
    }
}

// ---------------- GEMM phases (tensor-core mma; unchanged from R13) ----------------
template <int D>
__device__ void ph_fused_gemm(const float* __restrict__ X0, const float* __restrict__ X1,
                              const float* __restrict__ X2, const float* __restrict__ W,
                              const float* __restrict__ bias,
                              const float* __restrict__ Wt, const float* __restrict__ Wp,
                              const float* __restrict__ bt, const float* __restrict__ bp,
                              float* __restrict__ U, __half* __restrict__ V16, int n,
                              __half (*XH)[XS], __half (*WS)[XS]) {
    const int tid = threadIdx.x, l = tid & 31, w = tid >> 5;
    const int m0 = (w & 3) * 16, n0 = (w >> 2) * 32;
    const int r1 = m0 + (l >> 2), r2 = r1 + 8;
    const int ntiles = (n + 63) >> 6;
    for (int t = blockIdx.x; t < ntiles; t += gridDim.x) {
        const int node0 = t * 64;
        float cf[4][4];
#pragma unroll
        for (int j4 = 0; j4 < 4; j4++) {
            int c = n0 + 8 * j4 + (l & 3) * 2;
            float b0 = __ldg(&bias[c]), b1 = __ldg(&bias[c + 1]);
            cf[j4][0] = b0; cf[j4][1] = b1; cf[j4][2] = b0; cf[j4][3] = b1;
        }
        const float* Xsrc[3] = {X0, X1, X2};
#pragma unroll
        for (int j = 0; j < 3; j++) {
            __syncthreads();
            load_xtile16<D>(Xsrc[j], node0, n, XH);
            load_wtile16<D>(W + j * D * 64, WS);
            __syncthreads();
            mma_sweep<D>(cf, (const __half (*)[XS])XH, (const __half (*)[XS])WS, m0, n0);
        }
        __syncthreads();
        // relu -> H (fp16) in XH; load Wt+Wp
#pragma unroll
        for (int j4 = 0; j4 < 4; j4++) {
            int c = n0 + 8 * j4 + (l & 3) * 2;
            *(half2*)&XH[r1][c] = __floats2half2_rn(fmaxf(cf[j4][0], 0.f), fmaxf(cf[j4][1], 0.f));
            *(half2*)&XH[r2][c] = __floats2half2_rn(fmaxf(cf[j4][2], 0.f), fmaxf(cf[j4][3], 0.f));
        }
        load_wtile16_sum(Wt, Wp, WS);
        __syncthreads();
#pragma unroll
        for (int j4 = 0; j4 < 4; j4++) {
            int c = n0 + 8 * j4 + (l & 3) * 2;
            float b0 = __ldg(&bt[c]) + __ldg(&bp[c]);
            float b1 = __ldg(&bt[c + 1]) + __ldg(&bp[c + 1]);
            cf[j4][0] = b0; cf[j4][1] = b1; cf[j4][2] = b0; cf[j4][3] = b1;
        }
        mma_sweep<64>(cf, (const __half (*)[XS])XH, (const __half (*)[XS])WS, m0, n0);
#pragma unroll
        for (int j4 = 0; j4 < 4; j4++) {
            int c = n0 + 8 * j4 + (l & 3) * 2;
            if (node0 + r1 < n)
                *(float2*)&U[(size_t)(node0 + r1) * 64 + c] = make_float2(cf[j4][0], cf[j4][1]);
            if (node0 + r2 < n)
                *(float2*)&U[(size_t)(node0 + r2) * 64 + c] = make_float2(cf[j4][2], cf[j4][3]);
        }
        __syncthreads();
        load_wtile16<64>(Wt, WS);
        __syncthreads();
#pragma unroll
        for (int j4 = 0; j4 < 4; j4++) {
            cf[j4][0] = 0.f; cf[j4][1] = 0.f; cf[j4][2] = 0.f; cf[j4][3] = 0.f;
        }
        mma_sweep<64>(cf, (const __half (*)[XS])XH, (const __half (*)[XS])WS, m0, n0);
#pragma unroll
        for (int j4 = 0; j4 < 4; j4++) {
            int c = n0 + 8 * j4 + (l & 3) * 2;
            if (node0 + r1 < n)
                *(half2*)&V16[(size_t)(node0 + r1) * 64 + c] = __floats2half2_rn(cf[j4][0], cf[j4][1]);
            if (node0 + r2 < n)
                *(half2*)&V16[(size_t)(node0 + r2) * 64 + c] = __floats2half2_rn(cf[j4][2], cf[j4][3]);
        }
        __syncthreads();
    }
}

__device__ void ph_cheb_gemm(const float* __restrict__ X0, const float* __restrict__ X1,
                             const float* __restrict__ X2, const float* __restrict__ W,
                             const float* __restrict__ bias, float* __restrict__ out, int n,
                             __half (*XH)[XS], __half (*WS)[XS]) {
    const int tid = threadIdx.x, l = tid & 31, w = tid >> 5;
    const int m0 = (w & 3) * 16, n0 = (w >> 2) * 32;
    const int r1 = m0 + (l >> 2), r2 = r1 + 8;
    const int ntiles = (n + 63) >> 6;
    for (int t = blockIdx.x; t < ntiles; t += gridDim.x) {
        const int node0 = t * 64;
        float cf[4][4];
#pragma unroll
        for (int j4 = 0; j4 < 4; j4++) {
            int c = n0 + 8 * j4 + (l & 3) * 2;
            float b0 = __ldg(&bias[c]), b1 = __ldg(&bias[c + 1]);
            cf[j4][0] = b0; cf[j4][1] = b1; cf[j4][2] = b0; cf[j4][3] = b1;
        }
        const float* Xsrc[3] = {X0, X1, X2};
#pragma unroll
        for (int j = 0; j < 3; j++) {
            __syncthreads();
            load_xtile16<64>(Xsrc[j], node0, n, XH);
            load_wtile16<64>(W + j * 4096, WS);
            __syncthreads();
            mma_sweep<64>(cf, (const __half (*)[XS])XH, (const __half (*)[XS])WS, m0, n0);
        }
#pragma unroll
        for (int j4 = 0; j4 < 4; j4++) {
            int c = n0 + 8 * j4 + (l & 3) * 2;
            if (node0 + r1 < n)
                *(float2*)&out[(size_t)(node0 + r1) * 64 + c] =
                    make_float2(fmaxf(cf[j4][0], 0.f), fmaxf(cf[j4][1], 0.f));
            if (node0 + r2 < n)
                *(float2*)&out[(size_t)(node0 + r2) * 64 + c] =
                    make_float2(fmaxf(cf[j4][2], 0.f), fmaxf(cf[j4][3], 0.f));
        }
        __syncthreads();
    }
}

// ---------------- the single persistent kernel ----------------
__global__ void __launch_bounds__(256, 6) mega_kernel(
    const float* __restrict__ feat, const int* __restrict__ src,
    const int* __restrict__ dst, const int* __restrict__ gid,
    const float* __restrict__ W1, const float* __restrict__ b1,
    const float* __restrict__ W2, const float* __restrict__ b2,
    const float* __restrict__ W3, const float* __restrict__ b3,
    const float* __restrict__ Wt1, const float* __restrict__ bt1,
    const float* __restrict__ Wp1, const float* __restrict__ bp1,
    const float* __restrict__ Wt2, const float* __restrict__ bt2,
    const float* __restrict__ Wp2, const float* __restrict__ bp2,
    float* __restrict__ out, int n, int e, int G) {
    __shared__ __align__(16) __half sX16[64][XS];
    __shared__ __align__(16) __half sW16[64][XS];
    __shared__ int s_ws[9];
    __shared__ int s_run;

    const int nb = gridDim.x;
    const int tid = threadIdx.x;
    const int lane = tid & 31, wid = tid >> 5;
    const int gtid = blockIdx.x * 256 + tid;
    const int nthreads = nb * 256;
    const int gw = blockIdx.x * 8 + wid;
    const int nwarps = nb * 8;

    // ---- B: degree count + fp16 copy of input features ----
    for (int i = gtid; i < e; i += nthreads) atomicAdd(&g_deg[dst[i]], 1);
    for (int i = gtid; i < n * 16; i += nthreads) g_feat16[i] = __float2half(feat[i]);
    gsync(nb);

    // ---- C1: per-block exclusive scan; zero pooling accumulators ----
    for (int i = gtid; i < G * 64; i += nthreads) g_gsum[i] = 0.f;
    for (int i = gtid; i < G; i += nthreads) g_gcnt[i] = 0;
    const int per = (n + nb - 1) / nb;
    const int rng0 = blockIdx.x * per;
    const int rng1 = min(n, rng0 + per);
    if (tid == 0) s_run = 0;
    __syncthreads();
    for (int t0 = rng0; t0 < rng1; t0 += 1024) {
        int base = t0 + tid * 4;
        int v[4]; int s = 0;
#pragma unroll
        for (int j = 0; j < 4; j++) { int i = base + j; v[j] = (i < rng1) ? g_deg[i] : 0; s += v[j]; }
        int inc = s;
#pragma unroll
        for (int o = 1; o < 32; o <<= 1) { int x = __shfl_up_sync(0xFFFFFFFFu, inc, o); if (lane >= o) inc += x; }
        if (lane == 31) s_ws[wid] = inc;
        __syncthreads();
        if (wid == 0) {
            int w = (lane < 8) ? s_ws[lane] : 0;
            int winc = w;
#pragma unroll
            for (int o = 1; o < 8; o <<= 1) { int x = __shfl_up_sync(0xFFFFFFFFu, winc, o); if (lane >= o) winc += x; }
            if (lane < 8) s_ws[lane] = winc - w;
            if (lane == 7) s_ws[8] = winc;
        }
        __syncthreads();
        int off = s_run + s_ws[wid] + (inc - s);
#pragma unroll
        for (int j = 0; j < 4; j++) { int i = base + j; if (i < rng1) { g_rowptr[i] = off; off += v[j]; } }
        __syncthreads();
        if (tid == 0) s_run += s_ws[8];
        __syncthreads();
    }
    if (tid == 0) g_bsums[blockIdx.x] = s_run;
    gsync(nb);

    // ---- C3: block 0 scans block totals (nb <= 1024) ----
    if (blockIdx.x == 0) {
        int base = tid * 4;
        int v[4]; int s = 0;
#pragma unroll
        for (int j = 0; j < 4; j++) { int i = base + j; v[j] = (i < nb) ? g_bsums[i] : 0; s += v[j]; }
        int inc = s;
#pragma unroll
        for (int o = 1; o < 32; o <<= 1) { int x = __shfl_up_sync(0xFFFFFFFFu, inc, o); if (lane >= o) inc += x; }
        if (lane == 31) s_ws[wid] = inc;
        __syncthreads();
        if (wid == 0) {
            int w = (lane < 8) ? s_ws[lane] : 0;
            int winc = w;
#pragma unroll
            for (int o = 1; o < 8; o <<= 1) { int x = __shfl_up_sync(0xFFFFFFFFu, winc, o); if (lane >= o) winc += x; }
            if (lane < 8) s_ws[lane] = winc - w;
        }
        __syncthreads();
        int off = s_ws[wid] + (inc - s);
#pragma unroll
        for (int j = 0; j < 4; j++) { int i = base + j; if (i < nb) { g_bsums[i] = off; off += v[j]; } }
    }
    gsync(nb);

    // ---- C5: add block offsets; cursor; dinv; rowptr[n] ----
    {
        int off = g_bsums[blockIdx.x];
        for (int i = rng0 + tid; i < rng1; i += 256) {
            int r = g_rowptr[i] + off;
            g_rowptr[i] = r;
            g_cursor[i] = r;
            int d = g_deg[i];
            g_dinv[i] = (d > 0) ? rsqrtf((float)d) : 1.0f;
        }
        if (gtid == 0) g_rowptr[n] = e;
    }
    gsync(nb);

    // ---- D: fill CSR (interleaved col+weight) ----
    for (int i = gtid; i < e; i += nthreads) {
        int d = dst[i], s = src[i];
        int p = atomicAdd(&g_cursor[d], 1);
        g_cew[p] = make_int2(s, __float_as_int(g_dinv[s]));
    }
    gsync(nb);

    // ---- Layer 1 (Cheb 16->64): X1 = -aggr(feat), X2 = -2*aggr(X1) - feat ----
    ph_aggr16h(g_feat16, nullptr, g_B1, g_x116, -1.f, 0.f, n, gw, nwarps);
    gsync(nb);
    ph_aggr16h(g_x116, feat, g_B2, nullptr, -2.f, -1.f, n, gw, nwarps);
    gsync(nb);
    ph_fused_gemm<16>(feat, g_B1, g_B2, W1, b1, Wt1, Wp1, bt1, bp1, g_B3, g_F1, n, sX16, sW16);
    gsync(nb);
    ph_edge_minh(g_B3, g_F1, g_B1, g_F2, n, gw, nwarps);     // H2 -> B1 + F2
    gsync(nb);

    // ---- Layer 3 (Cheb 64->64) ----
    ph_aggr64h(g_F2, nullptr, g_B2, g_F1, -1.f, 0.f, n, gw, nwarps);   // X1 -> B2 + F1
    gsync(nb);
    ph_aggr64h(g_F1, g_B1, g_B3, nullptr, -2.f, -1.f, n, gw, nwarps);  // X2 -> B3
    gsync(nb);
    ph_fused_gemm<64>(g_B1, g_B2, g_B3, W2, b2, Wt2, Wp2, bt2, bp2, g_B2, g_F1, n, sX16, sW16);
    gsync(nb);
    ph_edge_minh(g_B2, g_F1, g_B1, g_F2, n, gw, nwarps);     // H4 -> B1 + F2
    gsync(nb);

    // ---- Layer 5 (Cheb 64->64) ----
    ph_aggr64h(g_F2, nullptr, g_B2, g_F1, -1.f, 0.f, n, gw, nwarps);   // X1 -> B2 + F1
    gsync(nb);
    ph_aggr64h(g_F1, g_B1, g_B3, nullptr, -2.f, -1.f, n, gw, nwarps);  // X2 -> B3
    gsync(nb);
    ph_cheb_gemm(g_B1, g_B2, g_B3, W3, b3, g_B4, n, sX16, sW16);
    gsync(nb);

    // ---- Pool: per-graph mean (graph_ids sorted) ----
    {
        int chunk = (n + nwarps - 1) / nwarps;
        int pbeg = gw * chunk, pend = min(n, pbeg + chunk);
        if (pbeg < pend) {
            float sx = 0.f, sy = 0.f;
            int cur = gid[pbeg]; int cnt = 0;
            for (int i = pbeg; i < pend; i++) {
                int g = gid[i];
                if (g != cur) {
                    atomicAdd(&g_gsum[cur * 64 + lane * 2], sx);
                    atomicAdd(&g_gsum[cur * 64 + lane * 2 + 1], sy);
                    if (lane == 0) atomicAdd(&g_gcnt[cur], cnt);
                    sx = 0.f; sy = 0.f; cnt = 0; cur = g;
                }
                float2 v = *(const float2*)(g_B4 + (size_t)i * 64 + lane * 2);
                sx += v.x; sy += v.y; cnt++;
            }
            atomicAdd(&g_gsum[cur * 64 + lane * 2], sx);
            atomicAdd(&g_gsum[cur * 64 + lane * 2 + 1], sy);
            if (lane == 0) atomicAdd(&g_gcnt[cur], cnt);
        }
    }
    gsync(nb);

    // ---- Finalize: write output + reset g_deg for next replay ----
    for (int i = gtid; i < G * 64; i += nthreads) {
        int c = g_gcnt[i >> 6];
        out[i] = g_gsum[i] / (c > 0 ? (float)c : 1.0f);
    }
    for (int i = gtid; i < n; i += nthreads) g_deg[i] = 0;
}

// ---------------- launch ----------------
extern "C" void kernel_launch(void* const* d_in, const int* in_sizes, int n_in,
                              void* d_out, int out_size) {
    const float* feat = (const float*)d_in[0];
    const int*   src  = (const int*)d_in[1];
    const int*   dst  = (const int*)d_in[2];
    const int*   gid  = (const int*)d_in[3];
    const float* W1 = (const float*)d_in[4];  const float* b1 = (const float*)d_in[5];
    const float* W2 = (const float*)d_in[6];  const float* b2 = (const float*)d_in[7];
    const float* W3 = (const float*)d_in[8];  const float* b3 = (const float*)d_in[9];
    const float* Wt1 = (const float*)d_in[10]; const float* bt1 = (const float*)d_in[11];
    const float* Wp1 = (const float*)d_in[12]; const float* bp1 = (const float*)d_in[13];
    const float* Wt2 = (const float*)d_in[14]; const float* bt2 = (const float*)d_in[15];
    const float* Wp2 = (const float*)d_in[16]; const float* bp2 = (const float*)d_in[17];
    float* out = (float*)d_out;

    const int n = in_sizes[0] / 16;
    const int e = in_sizes[1];
    const int G = out_size / 64;

    int dev = 0;
    cudaGetDevice(&dev);
    int sms = 0;
    cudaDeviceGetAttribute(&sms, cudaDevAttrMultiProcessorCount, dev);
    if (sms <= 0) sms = 148;
    int perSM = 0;
    cudaOccupancyMaxActiveBlocksPerMultiprocessor(&perSM, mega_kernel, 256, 0);
    if (perSM <= 0) perSM = 1;
    int grid = sms * perSM;
    if (grid > MAXB) grid = MAXB;

    mega_kernel<<<grid, 256>>>(feat, src, dst, gid,
                               W1, b1, W2, b2, W3, b3,
                               Wt1, bt1, Wp1, bp1, Wt2, bt2, Wp2, bp2,
                               out, n, e, G);
}

// round 17
// speedup vs baseline: 1.5300x; 1.5300x over previous
#include <cuda_runtime.h>
#include <cuda_fp16.h>
#include <cstdint>
#include <math.h>

#define MAXN 100000
#define MAXE 1600000
#define MAXG 128
#define MAXB 1024
#define XS 72   // half-element stride of smem tiles (144B rows: conflict-free ldmatrix)

// ---------------- scratch (static __device__ — zero-initialized at load) ----------------
__device__ int   g_deg[MAXN];          // zeroed by finalize of previous replay (and at load)
__device__ float g_dinv[MAXN];
__device__ int   g_rowptr[MAXN + 1];
__device__ int   g_cursor[MAXN];
__device__ int2  g_cew[MAXE];          // (col, bitcast weight)
__device__ int   g_bsums[MAXB];
__device__ float g_B1[(size_t)MAXN * 64];
__device__ float g_B2[(size_t)MAXN * 64];
__device__ float g_B3[(size_t)MAXN * 64];
__device__ float g_B4[(size_t)MAXN * 64];
__device__ __half g_F1[(size_t)MAXN * 64];   // fp16 gather operands
__device__ __half g_F2[(size_t)MAXN * 64];
__device__ __half g_feat16[(size_t)MAXN * 16];
__device__ __half g_x116[(size_t)MAXN * 16];
__device__ float g_gsum[MAXG * 64];
__device__ int   g_gcnt[MAXG];
__device__ unsigned g_epoch;
__device__ unsigned g_cnt;

// ---------------- half2 <-> float helpers ----------------
__device__ __forceinline__ float2 h2f(unsigned u) {
    __half2 h = *reinterpret_cast<__half2*>(&u);
    return __half22float2(h);
}
__device__ __forceinline__ unsigned f2h(float a, float b) {
    __half2 h = __floats2half2_rn(a, b);
    return *reinterpret_cast<unsigned*>(&h);
}

// ---------------- tensor-core primitives ----------------
__device__ __forceinline__ uint32_t smem_u32(const void* p) {
    return (uint32_t)__cvta_generic_to_shared(p);
}
__device__ __forceinline__ void ldsm_x4(unsigned r[4], uint32_t addr) {
    asm volatile("ldmatrix.sync.aligned.m8n8.x4.shared.b16 {%0,%1,%2,%3}, [%4];"
                 : "=r"(r[0]), "=r"(r[1]), "=r"(r[2]), "=r"(r[3]) : "r"(addr));
}
__device__ __forceinline__ void ldsm_x4t(unsigned r[4], uint32_t addr) {
    asm volatile("ldmatrix.sync.aligned.m8n8.x4.trans.shared.b16 {%0,%1,%2,%3}, [%4];"
                 : "=r"(r[0]), "=r"(r[1]), "=r"(r[2]), "=r"(r[3]) : "r"(addr));
}
__device__ __forceinline__ void mma16816(float c[4], const unsigned a[4], const unsigned b[2]) {
    asm volatile("mma.sync.aligned.m16n8k16.row.col.f32.f16.f16.f32 "
                 "{%0,%1,%2,%3}, {%4,%5,%6,%7}, {%8,%9}, {%0,%1,%2,%3};"
                 : "+f"(c[0]), "+f"(c[1]), "+f"(c[2]), "+f"(c[3])
                 : "r"(a[0]), "r"(a[1]), "r"(a[2]), "r"(a[3]), "r"(b[0]), "r"(b[1]));
}

// one k-step (k..k+15) for this warp's 16x32 output block
__device__ __forceinline__ void mma_step(float (*cf)[4], const __half (*XH)[XS],
                                         const __half (*WS)[XS], int m0, int n0, int k) {
    const int l = threadIdx.x & 31;
    unsigned a[4], b0[4], b1[4];
    int arow = m0 + (l & 7) + ((l >> 3) & 1) * 8;
    int acol = k + (l >> 4) * 8;
    ldsm_x4(a, smem_u32(&XH[arow][acol]));
    int brow = k + (l & 7) + ((l >> 3) & 1) * 8;
    int bc = (l >> 4) * 8;
    ldsm_x4t(b0, smem_u32(&WS[brow][n0 + bc]));
    ldsm_x4t(b1, smem_u32(&WS[brow][n0 + 16 + bc]));
    mma16816(cf[0], a, &b0[0]);
    mma16816(cf[1], a, &b0[2]);
    mma16816(cf[2], a, &b1[0]);
    mma16816(cf[3], a, &b1[2]);
}

template <int D>
__device__ __forceinline__ void mma_sweep(float (*cf)[4], const __half (*XH)[XS],
                                          const __half (*WS)[XS], int m0, int n0) {
#pragma unroll
    for (int k = 0; k < D; k += 16) mma_step(cf, XH, WS, m0, n0, k);
}

// fp32 global -> fp16 smem tile (64 x D), zero-padded rows beyond n
template <int D>
__device__ __forceinline__ void load_xtile16(const float* __restrict__ Xj, int node0, int n,
                                             __half (*XH)[XS]) {
    const int tid = threadIdx.x;
    for (int i = tid; i < 64 * (D / 2); i += 256) {
        int m = i / (D / 2), q = i % (D / 2);
        int nn = node0 + m;
        float2 v = make_float2(0.f, 0.f);
        if (nn < n) v = *(const float2*)&Xj[(size_t)nn * D + 2 * q];
        *(half2*)&XH[m][2 * q] = __floats2half2_rn(v.x, v.y);
    }
}

template <int D>
__device__ __forceinline__ void load_wtile16(const float* __restrict__ W, __half (*WS)[XS]) {
    const int tid = threadIdx.x;
    for (int i = tid; i < D * 32; i += 256) {
        int k = i >> 5, q = i & 31;
        float2 v = *(const float2*)&W[k * 64 + 2 * q];
        *(half2*)&WS[k][2 * q] = __floats2half2_rn(v.x, v.y);
    }
}

__device__ __forceinline__ void load_wtile16_sum(const float* __restrict__ A,
                                                 const float* __restrict__ B, __half (*WS)[XS]) {
    const int tid = threadIdx.x;
    for (int i = tid; i < 64 * 32; i += 256) {
        int k = i >> 5, q = i & 31;
        float2 a = *(const float2*)&A[k * 64 + 2 * q];
        float2 b = *(const float2*)&B[k * 64 + 2 * q];
        *(half2*)&WS[k][2 * q] = __floats2half2_rn(a.x + b.x, a.y + b.y);
    }
}

// ---------------- grid-wide barrier ----------------
__device__ __forceinline__ void gsync(int nb) {
    __syncthreads();
    if (threadIdx.x == 0) {
        __threadfence();                       // release
        volatile unsigned* ep = &g_epoch;
        unsigned e = *ep;
        if (atomicAdd(&g_cnt, 1u) == (unsigned)(nb - 1)) {
            g_cnt = 0;
            __threadfence();
            *ep = e + 1;
        } else {
            while (*ep == e) {}
            __threadfence();                   // acquire
        }
    }
    __syncthreads();
}

// ---------------- gather phases (fp16 operands; 16 lanes x uint2 per edge) ----------------
__device__ void ph_aggr64h(const __half* __restrict__ f16, const float* __restrict__ extra,
                           float* __restrict__ out, __half* __restrict__ out16,
                           float alpha, float beta, int n, int gw, int nwarps) {
    const int lane = threadIdx.x & 31;
    const int sub = lane >> 4;
    const int c = (lane & 15) * 4;
    for (int node = gw; node < n; node += nwarps) {
        const int beg = g_rowptr[node], end = g_rowptr[node + 1];
        float4 acc = make_float4(0.f, 0.f, 0.f, 0.f);
        for (int e = beg; e < end; e += 4) {
            int e0 = e + sub, e1 = e + 2 + sub;
            bool v0 = e0 < end, v1 = e1 < end;
            int2 ce0 = v0 ? g_cew[e0] : make_int2(0, 0);
            int2 ce1 = v1 ? g_cew[e1] : make_int2(0, 0);
            float w0 = __int_as_float(ce0.y), w1 = __int_as_float(ce1.y);
            uint2 r0 = *(const uint2*)(f16 + (size_t)ce0.x * 64 + c);
            uint2 r1 = *(const uint2*)(f16 + (size_t)ce1.x * 64 + c);
            float2 a0 = h2f(r0.x), a1 = h2f(r0.y);
            float2 b0 = h2f(r1.x), b1 = h2f(r1.y);
            acc.x = fmaf(w0, a0.x, acc.x); acc.y = fmaf(w0, a0.y, acc.y);
            acc.z = fmaf(w0, a1.x, acc.z); acc.w = fmaf(w0, a1.y, acc.w);
            acc.x = fmaf(w1, b0.x, acc.x); acc.y = fmaf(w1, b0.y, acc.y);
            acc.z = fmaf(w1, b1.x, acc.z); acc.w = fmaf(w1, b1.y, acc.w);
        }
        acc.x += __shfl_xor_sync(0xFFFFFFFFu, acc.x, 16);
        acc.y += __shfl_xor_sync(0xFFFFFFFFu, acc.y, 16);
        acc.z += __shfl_xor_sync(0xFFFFFFFFu, acc.z, 16);
        acc.w += __shfl_xor_sync(0xFFFFFFFFu, acc.w, 16);
        if (sub == 0) {
            float s = alpha * g_dinv[node];
            float4 r = make_float4(s * acc.x, s * acc.y, s * acc.z, s * acc.w);
            if (extra) {
                float4 ex = *(const float4*)(extra + (size_t)node * 64 + c);
                r.x = fmaf(beta, ex.x, r.x); r.y = fmaf(beta, ex.y, r.y);
                r.z = fmaf(beta, ex.z, r.z); r.w = fmaf(beta, ex.w, r.w);
            }
            *(float4*)(out + (size_t)node * 64 + c) = r;
            if (out16)
                *(uint2*)(out16 + (size_t)node * 64 + c) =
                    make_uint2(f2h(r.x, r.y), f2h(r.z, r.w));
        }
    }
}

__device__ void ph_aggr16h(const __half* __restrict__ f16, const float* __restrict__ extra,
                           float* __restrict__ out, __half* __restrict__ out16,
                           float alpha, float beta, int n, int gw, int nwarps) {
    const int lane = threadIdx.x & 31;
    const int sub = lane >> 2;
    const int c = (lane & 3) * 4;
    for (int node = gw; node < n; node += nwarps) {
        const int beg = g_rowptr[node], end = g_rowptr[node + 1];
        float4 acc = make_float4(0.f, 0.f, 0.f, 0.f);
        for (int e = beg; e < end; e += 8) {
            int ee = e + sub;
            bool v = ee < end;
            int2 ce = v ? g_cew[ee] : make_int2(0, 0);
            float w = __int_as_float(ce.y);
            uint2 r0 = *(const uint2*)(f16 + (size_t)ce.x * 16 + c);
            float2 a0 = h2f(r0.x), a1 = h2f(r0.y);
            acc.x = fmaf(w, a0.x, acc.x); acc.y = fmaf(w, a0.y, acc.y);
            acc.z = fmaf(w, a1.x, acc.z); acc.w = fmaf(w, a1.y, acc.w);
        }
#pragma unroll
        for (int o = 4; o < 32; o <<= 1) {
            acc.x += __shfl_xor_sync(0xFFFFFFFFu, acc.x, o);
            acc.y += __shfl_xor_sync(0xFFFFFFFFu, acc.y, o);
            acc.z += __shfl_xor_sync(0xFFFFFFFFu, acc.z, o);
            acc.w += __shfl_xor_sync(0xFFFFFFFFu, acc.w, o);
        }
        if (lane < 4) {
            float s = alpha * g_dinv[node];
            float4 r = make_float4(s * acc.x, s * acc.y, s * acc.z, s * acc.w);
            if (extra) {
                float4 ex = *(const float4*)(extra + (size_t)node * 16 + c);
                r.x = fmaf(beta, ex.x, r.x); r.y = fmaf(beta, ex.y, r.y);
                r.z = fmaf(beta, ex.z, r.z); r.w = fmaf(beta, ex.w, r.w);
            }
            *(float4*)(out + (size_t)node * 16 + c) = r;
            if (out16)
                *(uint2*)(out16 + (size_t)node * 16 + c) =
                    make_uint2(f2h(r.x, r.y), f2h(r.z, r.w));
        }
    }
}

__device__ void ph_edge_minh(const float* __restrict__ U, const __half* __restrict__ V16,
                             float* __restrict__ out, __half* __restrict__ out16,
                             int n, int gw, int nwarps) {
    const int lane = threadIdx.x & 31;
    const int sub = lane >> 4;
    const int c = (lane & 15) * 4;
    const float INF = 3.4e38f;
    for (int node = gw; node < n; node += nwarps) {
        const int beg = g_rowptr[node], end = g_rowptr[node + 1];
        float4 mn = make_float4(INF, INF, INF, INF);
        for (int e = beg; e < end; e += 4) {
            int e0 = e + sub, e1 = e + 2 + sub;
            if (e0 < end) {
                int s0 = g_cew[e0].x;
                uint2 r0 = *(const uint2*)(V16 + (size_t)s0 * 64 + c);
                float2 a0 = h2f(r0.x), a1 = h2f(r0.y);
                mn.x = fminf(mn.x, a0.x); mn.y = fminf(mn.y, a0.y);
                mn.z = fminf(mn.z, a1.x); mn.w = fminf(mn.w, a1.y);
            }
            if (e1 < end) {
                int s1 = g_cew[e1].x;
                uint2 r1 = *(const uint2*)(V16 + (size_t)s1 * 64 + c);
                float2 b0 = h2f(r1.x), b1 = h2f(r1.y);
                mn.x = fminf(mn.x, b0.x); mn.y = fminf(mn.y, b0.y);
                mn.z = fminf(mn.z, b1.x); mn.w = fminf(mn.w, b1.y);
            }
        }
        mn.x = fminf(mn.x, __shfl_xor_sync(0xFFFFFFFFu, mn.x, 16));
        mn.y = fminf(mn.y, __shfl_xor_sync(0xFFFFFFFFu, mn.y, 16));
        mn.z = fminf(mn.z, __shfl_xor_sync(0xFFFFFFFFu, mn.z, 16));
        mn.w = fminf(mn.w, __shfl_xor_sync(0xFFFFFFFFu, mn.w, 16));
        if (sub == 0) {
            float4 r = make_float4(0.f, 0.f, 0.f, 0.f);
            if (end > beg) {
                float4 u = *(const float4*)(U + (size_t)node * 64 + c);
                r.x = fmaxf(u.x - mn.x, 0.f); r.y = fmaxf(u.y - mn.y, 0.f);
                r.z = fmaxf(u.z - mn.z, 0.f); r.w = fmaxf(u.w - mn.w, 0.f);
            }
            *(float4*)(out + (size_t)node * 64 + c) = r;
            *(uint2*)(out16 + (size_t)node * 64 + c) =
                make_uint2(f2h(r.x, r.y), f2h(r.z, r.w));
        }
    }
}

// ---------------- GEMM phases (tensor-core mma; unchanged from R13) ----------------
template <int D>
__device__ void ph_fused_gemm(const float* __restrict__ X0, const float* __restrict__ X1,
                              const float* __restrict__ X2, const float* __restrict__ W,
                              const float* __restrict__ bias,
                              const float* __restrict__ Wt, const float* __restrict__ Wp,
                              const float* __restrict__ bt, const float* __restrict__ bp,
                              float* __restrict__ U, __half* __restrict__ V16, int n,
                              __half (*XH)[XS], __half (*WS)[XS]) {
    const int tid = threadIdx.x, l = tid & 31, w = tid >> 5;
    const int m0 = (w & 3) * 16, n0 = (w >> 2) * 32;
    const int r1 = m0 + (l >> 2), r2 = r1 + 8;
    const int ntiles = (n + 63) >> 6;
    for (int t = blockIdx.x; t < ntiles; t += gridDim.x) {
        const int node0 = t * 64;
        float cf[4][4];
#pragma unroll
        for (int j4 = 0; j4 < 4; j4++) {
            int c = n0 + 8 * j4 + (l & 3) * 2;
            float b0 = __ldg(&bias[c]), b1 = __ldg(&bias[c + 1]);
            cf[j4][0] = b0; cf[j4][1] = b1; cf[j4][2] = b0; cf[j4][3] = b1;
        }
        const float* Xsrc[3] = {X0, X1, X2};
#pragma unroll
        for (int j = 0; j < 3; j++) {
            __syncthreads();
            load_xtile16<D>(Xsrc[j], node0, n, XH);
            load_wtile16<D>(W + j * D * 64, WS);
            __syncthreads();
            mma_sweep<D>(cf, (const __half (*)[XS])XH, (const __half (*)[XS])WS, m0, n0);
        }
        __syncthreads();
        // relu -> H (fp16) in XH; load Wt+Wp
#pragma unroll
        for (int j4 = 0; j4 < 4; j4++) {
            int c = n0 + 8 * j4 + (l & 3) * 2;
            *(half2*)&XH[r1][c] = __floats2half2_rn(fmaxf(cf[j4][0], 0.f), fmaxf(cf[j4][1], 0.f));
            *(half2*)&XH[r2][c] = __floats2half2_rn(fmaxf(cf[j4][2], 0.f), fmaxf(cf[j4][3], 0.f));
        }
        load_wtile16_sum(Wt, Wp, WS);
        __syncthreads();
#pragma unroll
        for (int j4 = 0; j4 < 4; j4++) {
            int c = n0 + 8 * j4 + (l & 3) * 2;
            float b0 = __ldg(&bt[c]) + __ldg(&bp[c]);
            float b1 = __ldg(&bt[c + 1]) + __ldg(&bp[c + 1]);
            cf[j4][0] = b0; cf[j4][1] = b1; cf[j4][2] = b0; cf[j4][3] = b1;
        }
        mma_sweep<64>(cf, (const __half (*)[XS])XH, (const __half (*)[XS])WS, m0, n0);
#pragma unroll
        for (int j4 = 0; j4 < 4; j4++) {
            int c = n0 + 8 * j4 + (l & 3) * 2;
            if (node0 + r1 < n)
                *(float2*)&U[(size_t)(node0 + r1) * 64 + c] = make_float2(cf[j4][0], cf[j4][1]);
            if (node0 + r2 < n)
                *(float2*)&U[(size_t)(node0 + r2) * 64 + c] = make_float2(cf[j4][2], cf[j4][3]);
        }
        __syncthreads();
        load_wtile16<64>(Wt, WS);
        __syncthreads();
#pragma unroll
        for (int j4 = 0; j4 < 4; j4++) {
            cf[j4][0] = 0.f; cf[j4][1] = 0.f; cf[j4][2] = 0.f; cf[j4][3] = 0.f;
        }
        mma_sweep<64>(cf, (const __half (*)[XS])XH, (const __half (*)[XS])WS, m0, n0);
#pragma unroll
        for (int j4 = 0; j4 < 4; j4++) {
            int c = n0 + 8 * j4 + (l & 3) * 2;
            if (node0 + r1 < n)
                *(half2*)&V16[(size_t)(node0 + r1) * 64 + c] = __floats2half2_rn(cf[j4][0], cf[j4][1]);
            if (node0 + r2 < n)
                *(half2*)&V16[(size_t)(node0 + r2) * 64 + c] = __floats2half2_rn(cf[j4][2], cf[j4][3]);
        }
        __syncthreads();
    }
}

__device__ void ph_cheb_gemm(const float* __restrict__ X0, const float* __restrict__ X1,
                             const float* __restrict__ X2, const float* __restrict__ W,
                             const float* __restrict__ bias, float* __restrict__ out, int n,
                             __half (*XH)[XS], __half (*WS)[XS]) {
    const int tid = threadIdx.x, l = tid & 31, w = tid >> 5;
    const int m0 = (w & 3) * 16, n0 = (w >> 2) * 32;
    const int r1 = m0 + (l >> 2), r2 = r1 + 8;
    const int ntiles = (n + 63) >> 6;
    for (int t = blockIdx.x; t < ntiles; t += gridDim.x) {
        const int node0 = t * 64;
        float cf[4][4];
#pragma unroll
        for (int j4 = 0; j4 < 4; j4++) {
            int c = n0 + 8 * j4 + (l & 3) * 2;
            float b0 = __ldg(&bias[c]), b1 = __ldg(&bias[c + 1]);
            cf[j4][0] = b0; cf[j4][1] = b1; cf[j4][2] = b0; cf[j4][3] = b1;
        }
        const float* Xsrc[3] = {X0, X1, X2};
#pragma unroll
        for (int j = 0; j < 3; j++) {
            __syncthreads();
            load_xtile16<64>(Xsrc[j], node0, n, XH);
            load_wtile16<64>(W + j * 4096, WS);
            __syncthreads();
            mma_sweep<64>(cf, (const __half (*)[XS])XH, (const __half (*)[XS])WS, m0, n0);
        }
#pragma unroll
        for (int j4 = 0; j4 < 4; j4++) {
            int c = n0 + 8 * j4 + (l & 3) * 2;
            if (node0 + r1 < n)
                *(float2*)&out[(size_t)(node0 + r1) * 64 + c] =
                    make_float2(fmaxf(cf[j4][0], 0.f), fmaxf(cf[j4][1], 0.f));
            if (node0 + r2 < n)
                *(float2*)&out[(size_t)(node0 + r2) * 64 + c] =
                    make_float2(fmaxf(cf[j4][2], 0.f), fmaxf(cf[j4][3], 0.f));
        }
        __syncthreads();
    }
}

// ---------------- the single persistent kernel ----------------
__global__ void __launch_bounds__(256, 6) mega_kernel(
    const float* __restrict__ feat, const int* __restrict__ src,
    const int* __restrict__ dst, const int* __restrict__ gid,
    const float* __restrict__ W1, const float* __restrict__ b1,
    const float* __restrict__ W2, const float* __restrict__ b2,
    const float* __restrict__ W3, const float* __restrict__ b3,
    const float* __restrict__ Wt1, const float* __restrict__ bt1,
    const float* __restrict__ Wp1, const float* __restrict__ bp1,
    const float* __restrict__ Wt2, const float* __restrict__ bt2,
    const float* __restrict__ Wp2, const float* __restrict__ bp2,
    float* __restrict__ out, int n, int e, int G) {
    __shared__ __align__(16) __half sX16[64][XS];
    __shared__ __align__(16) __half sW16[64][XS];
    __shared__ int s_ws[9];
    __shared__ int s_run;

    const int nb = gridDim.x;
    const int tid = threadIdx.x;
    const int lane = tid & 31, wid = tid >> 5;
    const int gtid = blockIdx.x * 256 + tid;
    const int nthreads = nb * 256;
    const int gw = blockIdx.x * 8 + wid;
    const int nwarps = nb * 8;

    // ---- B: degree count + fp16 copy of input features ----
    for (int i = gtid; i < e; i += nthreads) atomicAdd(&g_deg[dst[i]], 1);
    for (int i = gtid; i < n * 16; i += nthreads) g_feat16[i] = __float2half(feat[i]);
    gsync(nb);

    // ---- C1: per-block exclusive scan; zero pooling accumulators ----
    for (int i = gtid; i < G * 64; i += nthreads) g_gsum[i] = 0.f;
    for (int i = gtid; i < G; i += nthreads) g_gcnt[i] = 0;
    const int per = (n + nb - 1) / nb;
    const int rng0 = blockIdx.x * per;
    const int rng1 = min(n, rng0 + per);
    if (tid == 0) s_run = 0;
    __syncthreads();
    for (int t0 = rng0; t0 < rng1; t0 += 1024) {
        int base = t0 + tid * 4;
        int v[4]; int s = 0;
#pragma unroll
        for (int j = 0; j < 4; j++) { int i = base + j; v[j] = (i < rng1) ? g_deg[i] : 0; s += v[j]; }
        int inc = s;
#pragma unroll
        for (int o = 1; o < 32; o <<= 1) { int x = __shfl_up_sync(0xFFFFFFFFu, inc, o); if (lane >= o) inc += x; }
        if (lane == 31) s_ws[wid] = inc;
        __syncthreads();
        if (wid == 0) {
            int w = (lane < 8) ? s_ws[lane] : 0;
            int winc = w;
#pragma unroll
            for (int o = 1; o < 8; o <<= 1) { int x = __shfl_up_sync(0xFFFFFFFFu, winc, o); if (lane >= o) winc += x; }
            if (lane < 8) s_ws[lane] = winc - w;
            if (lane == 7) s_ws[8] = winc;
        }
        __syncthreads();
        int off = s_run + s_ws[wid] + (inc - s);
#pragma unroll
        for (int j = 0; j < 4; j++) { int i = base + j; if (i < rng1) { g_rowptr[i] = off; off += v[j]; } }
        __syncthreads();
        if (tid == 0) s_run += s_ws[8];
        __syncthreads();
    }
    if (tid == 0) g_bsums[blockIdx.x] = s_run;
    gsync(nb);

    // ---- C3: block 0 scans block totals (nb <= 1024) ----
    if (blockIdx.x == 0) {
        int base = tid * 4;
        int v[4]; int s = 0;
#pragma unroll
        for (int j = 0; j < 4; j++) { int i = base + j; v[j] = (i < nb) ? g_bsums[i] : 0; s += v[j]; }
        int inc = s;
#pragma unroll
        for (int o = 1; o < 32; o <<= 1) { int x = __shfl_up_sync(0xFFFFFFFFu, inc, o); if (lane >= o) inc += x; }
        if (lane == 31) s_ws[wid] = inc;
        __syncthreads();
        if (wid == 0) {
            int w = (lane < 8) ? s_ws[lane] : 0;
            int winc = w;
#pragma unroll
            for (int o = 1; o < 8; o <<= 1) { int x = __shfl_up_sync(0xFFFFFFFFu, winc, o); if (lane >= o) winc += x; }
            if (lane < 8) s_ws[lane] = winc - w;
        }
        __syncthreads();
        int off = s_ws[wid] + (inc - s);
#pragma unroll
        for (int j = 0; j < 4; j++) { int i = base + j; if (i < nb) { g_bsums[i] = off; off += v[j]; } }
    }
    gsync(nb);

    // ---- C5: add block offsets; cursor; dinv; rowptr[n] ----
    {
        int off = g_bsums[blockIdx.x];
        for (int i = rng0 + tid; i < rng1; i += 256) {
            int r = g_rowptr[i] + off;
            g_rowptr[i] = r;
            g_cursor[i] = r;
            int d = g_deg[i];
            g_dinv[i] = (d > 0) ? rsqrtf((float)d) : 1.0f;
        }
        if (gtid == 0) g_rowptr[n] = e;
    }
    gsync(nb);

    // ---- D: fill CSR (interleaved col+weight) ----
    for (int i = gtid; i < e; i += nthreads) {
        int d = dst[i], s = src[i];
        int p = atomicAdd(&g_cursor[d], 1);
        g_cew[p] = make_int2(s, __float_as_int(g_dinv[s]));
    }
    gsync(nb);

    // ---- Layer 1 (Cheb 16->64): X1 = -aggr(feat), X2 = -2*aggr(X1) - feat ----
    ph_aggr16h(g_feat16, nullptr, g_B1, g_x116, -1.f, 0.f, n, gw, nwarps);
    gsync(nb);
    ph_aggr16h(g_x116, feat, g_B2, nullptr, -2.f, -1.f, n, gw, nwarps);
    gsync(nb);
    ph_fused_gemm<16>(feat, g_B1, g_B2, W1, b1, Wt1, Wp1, bt1, bp1, g_B3, g_F1, n, sX16, sW16);
    gsync(nb);
    ph_edge_minh(g_B3, g_F1, g_B1, g_F2, n, gw, nwarps);     // H2 -> B1 + F2
    gsync(nb);

    // ---- Layer 3 (Cheb 64->64) ----
    ph_aggr64h(g_F2, nullptr, g_B2, g_F1, -1.f, 0.f, n, gw, nwarps);   // X1 -> B2 + F1
    gsync(nb);
    ph_aggr64h(g_F1, g_B1, g_B3, nullptr, -2.f, -1.f, n, gw, nwarps);  // X2 -> B3
    gsync(nb);
    ph_fused_gemm<64>(g_B1, g_B2, g_B3, W2, b2, Wt2, Wp2, bt2, bp2, g_B2, g_F1, n, sX16, sW16);
    gsync(nb);
    ph_edge_minh(g_B2, g_F1, g_B1, g_F2, n, gw, nwarps);     // H4 -> B1 + F2
    gsync(nb);

    // ---- Layer 5 (Cheb 64->64) ----
    ph_aggr64h(g_F2, nullptr, g_B2, g_F1, -1.f, 0.f, n, gw, nwarps);   // X1 -> B2 + F1
    gsync(nb);
    ph_aggr64h(g_F1, g_B1, g_B3, nullptr, -2.f, -1.f, n, gw, nwarps);  // X2 -> B3
    gsync(nb);
    ph_cheb_gemm(g_B1, g_B2, g_B3, W3, b3, g_B4, n, sX16, sW16);
    gsync(nb);

    // ---- Pool: per-graph mean (graph_ids sorted) ----
    {
        int chunk = (n + nwarps - 1) / nwarps;
        int pbeg = gw * chunk, pend = min(n, pbeg + chunk);
        if (pbeg < pend) {
            float sx = 0.f, sy = 0.f;
            int cur = gid[pbeg]; int cnt = 0;
            for (int i = pbeg; i < pend; i++) {
                int g = gid[i];
                if (g != cur) {
                    atomicAdd(&g_gsum[cur * 64 + lane * 2], sx);
                    atomicAdd(&g_gsum[cur * 64 + lane * 2 + 1], sy);
                    if (lane == 0) atomicAdd(&g_gcnt[cur], cnt);
                    sx = 0.f; sy = 0.f; cnt = 0; cur = g;
                }
                float2 v = *(const float2*)(g_B4 + (size_t)i * 64 + lane * 2);
                sx += v.x; sy += v.y; cnt++;
            }
            atomicAdd(&g_gsum[cur * 64 + lane * 2], sx);
            atomicAdd(&g_gsum[cur * 64 + lane * 2 + 1], sy);
            if (lane == 0) atomicAdd(&g_gcnt[cur], cnt);
        }
    }
    gsync(nb);

    // ---- Finalize: write output + reset g_deg for next replay ----
    for (int i = gtid; i < G * 64; i += nthreads) {
        int c = g_gcnt[i >> 6];
        out[i] = g_gsum[i] / (c > 0 ? (float)c : 1.0f);
    }
    for (int i = gtid; i < n; i += nthreads) g_deg[i] = 0;
}

// ---------------- launch ----------------
extern "C" void kernel_launch(void* const* d_in, const int* in_sizes, int n_in,
                              void* d_out, int out_size) {
    const float* feat = (const float*)d_in[0];
    const int*   src  = (const int*)d_in[1];
    const int*   dst  = (const int*)d_in[2];
    const int*   gid  = (const int*)d_in[3];
    const float* W1 = (const float*)d_in[4];  const float* b1 = (const float*)d_in[5];
    const float* W2 = (const float*)d_in[6];  const float* b2 = (const float*)d_in[7];
    const float* W3 = (const float*)d_in[8];  const float* b3 = (const float*)d_in[9];
    const float* Wt1 = (const float*)d_in[10]; const float* bt1 = (const float*)d_in[11];
    const float* Wp1 = (const float*)d_in[12]; const float* bp1 = (const float*)d_in[13];
    const float* Wt2 = (const float*)d_in[14]; const float* bt2 = (const float*)d_in[15];
    const float* Wp2 = (const float*)d_in[16]; const float* bp2 = (const float*)d_in[17];
    float* out = (float*)d_out;

    const int n = in_sizes[0] / 16;
    const int e = in_sizes[1];
    const int G = out_size / 64;

    int dev = 0;
    cudaGetDevice(&dev);
    int sms = 0;
    cudaDeviceGetAttribute(&sms, cudaDevAttrMultiProcessorCount, dev);
    if (sms <= 0) sms = 148;
    int perSM = 0;
    cudaOccupancyMaxActiveBlocksPerMultiprocessor(&perSM, mega_kernel, 256, 0);
    if (perSM <= 0) perSM = 1;
    int grid = sms * perSM;
    if (grid > MAXB) grid = MAXB;

    mega_kernel<<<grid, 256>>>(feat, src, dst, gid,
                               W1, b1, W2, b2, W3, b3,
                               Wt1, bt1, Wp1, bp1, Wt2, bt2, Wp2, bp2,
                               out, n, e, G);
}